// round 14
// baseline (speedup 1.0000x reference)
#include <cuda_runtime.h>

// DenseDilatedKnnGraph: x (4,64,8192,1) fp32 -> edge_index (2,4,8192,9)
// k=9, dilation=1. Output buffer is FLOAT32 (confirmed: rel_err 0.0 in R8).
//
// R10: same 8x8 f32x2 register tile as R9, but 128-thread CTAs (4 warps ->
// one per SMSP; R9's 2-warp CTAs left SMSP2/3 idle, capping fma at 50%).
// QT=64 rows, CT=128 candidates, scan split across 2 threads/row + exact
// lexicographic (d2, idx) merge.

#define BB 4
#define DD 64
#define NN 8192
#define KK 9
#define CT 128         // candidates per tile
#define QT 64          // query rows per CTA
#define NTHR 128       // ty = tid>>4 (8 row-groups of 8), tx = tid&15 (16 cand-groups of 8)

typedef unsigned long long u64;

__device__ __align__(16) float g_ptsT[(size_t)BB * DD * NN];  // [b][d][n], 8 MB
__device__ float g_sq[BB * NN];

__device__ __forceinline__ u64 ffma2(u64 a, u64 b, u64 c) {
    u64 d;
    asm("fma.rn.f32x2 %0, %1, %2, %3;" : "=l"(d) : "l"(a), "l"(b), "l"(c));
    return d;
}
__device__ __forceinline__ u64 pack2(float v) {
    u64 d;
    asm("mov.b64 %0, {%1, %1};" : "=l"(d) : "f"(v));
    return d;
}
__device__ __forceinline__ float2 unpack2(u64 a) {
    float2 f;
    asm("mov.b64 {%0, %1}, %2;" : "=f"(f.x), "=f"(f.y) : "l"(a));
    return f;
}

// ---------------------------------------------------------------------------
// Stage 1: normalize + transpose to [b][d][n]. One thread per point.
// ---------------------------------------------------------------------------
__global__ void __launch_bounds__(256) normalize_kernel(const float* __restrict__ x) {
    int idx = blockIdx.x * blockDim.x + threadIdx.x;
    if (idx >= BB * NN) return;
    int b = idx / NN;
    int n = idx - b * NN;
    const float* xb = x + (size_t)b * DD * NN + n;
    float* pb = g_ptsT + (size_t)b * DD * NN + n;

    float v[DD];
    float s = 0.0f;
#pragma unroll
    for (int d = 0; d < DD; d++) {
        v[d] = xb[(size_t)d * NN];
        s += v[d] * v[d];
    }
    float nrm = fmaxf(sqrtf(s), 1e-12f);
    float s2 = 0.0f;
#pragma unroll
    for (int d = 0; d < DD; d++) {
        float xn = v[d] / nrm;
        pb[(size_t)d * NN] = xn;
        s2 += xn * xn;
    }
    g_sq[idx] = s2;
}

// ---------------------------------------------------------------------------
// Stage 2: tiled brute-force KNN, 128 threads (one warp per SMSP).
// ---------------------------------------------------------------------------
__global__ void __launch_bounds__(NTHR, 3) knn_kernel(float* __restrict__ out) {
    __shared__ __align__(16) float qs[QT * DD];   // [k][row]  16 KB (merge buf at end)
    __shared__ __align__(16) float cs[CT * DD];   // [k][cand] 32 KB; d2 tile after compute
    __shared__ float csq[CT];

    const int tid = threadIdx.x;
    const int ty = tid >> 4;          // 0..7  : rows ty*8 .. ty*8+7
    const int tx = tid & 15;          // 0..15 : cands tx*8 .. tx*8+7
    const int blk = blockIdx.x;       // 0..511
    const int b = blk >> 7;
    const int q0 = (blk & 127) << 6;  // 64 rows per CTA
    const float* __restrict__ ptsT = g_ptsT + (size_t)b * DD * NN;
    const size_t base = (size_t)b * NN;

    // q tile: qs[k][r] = ptsT[k][q0+r]; 1024 float4, 8 per thread, coalesced.
#pragma unroll
    for (int i = 0; i < 8; i++) {
        int f = tid + (i << 7);            // 0..1023
        int k = f >> 4, j4 = f & 15;
        ((float4*)qs)[f] = ((const float4*)(ptsT + (size_t)k * NN + q0))[j4];
    }
    float sqn[8];
#pragma unroll
    for (int rr = 0; rr < 8; rr++) sqn[rr] = g_sq[base + q0 + (ty << 3) + rr];

    // per-thread top-k stream: row (tid&63), candidate half (tid>>6)
    const int srow = tid & 63;
    const int half = tid >> 6;
    float bd[KK];
    int   bi[KK];
#pragma unroll
    for (int i = 0; i < KK; i++) { bd[i] = 3.4e38f; bi[i] = 0; }

    u64 acc[32];                       // [row_pair p 0..3][cand cc 0..7]
#pragma unroll
    for (int i = 0; i < 32; i++) acc[i] = 0ull;

    for (int t0 = 0; t0 < NN; t0 += CT) {
        __syncthreads();               // prev scan done; safe to overwrite cs
#pragma unroll
        for (int i = 0; i < 16; i++) {
            int f = tid + (i << 7);        // 0..2047 float4
            int k = f >> 5, j4 = f & 31;
            ((float4*)cs)[f] = ((const float4*)(ptsT + (size_t)k * NN + t0))[j4];
        }
        csq[tid] = g_sq[base + t0 + tid];
        __syncthreads();

        // ---- mainloop: 64 k-steps, 32 FFMA2 per step per thread
#pragma unroll 4
        for (int k = 0; k < DD; k++) {
            const float* qk = qs + (k << 6) + (ty << 3);
            ulonglong2 qA = *(const ulonglong2*)(qk);       // rows +0..3
            ulonglong2 qB = *(const ulonglong2*)(qk + 4);   // rows +4..7
            const float* ck = cs + (k << 7) + (tx << 3);
            float4 cA = *(const float4*)(ck);
            float4 cB = *(const float4*)(ck + 4);
            u64 cd[8];
            cd[0] = pack2(cA.x); cd[1] = pack2(cA.y);
            cd[2] = pack2(cA.z); cd[3] = pack2(cA.w);
            cd[4] = pack2(cB.x); cd[5] = pack2(cB.y);
            cd[6] = pack2(cB.z); cd[7] = pack2(cB.w);
#pragma unroll
            for (int c = 0; c < 8; c++) {
                acc[0 * 8 + c] = ffma2(qA.x, cd[c], acc[0 * 8 + c]);
                acc[1 * 8 + c] = ffma2(qA.y, cd[c], acc[1 * 8 + c]);
                acc[2 * 8 + c] = ffma2(qB.x, cd[c], acc[2 * 8 + c]);
                acc[3 * 8 + c] = ffma2(qB.y, cd[c], acc[3 * 8 + c]);
            }
        }
        __syncthreads();               // all reads of cs done

        // ---- epilogue: d2 -> swizzled smem aliasing cs (exactly 32 KB).
        // d2[r][c] lives at word c*64 + (r ^ (c>>3)).  Scatter <=2-way;
        // scan (lanes = 32 consecutive r, const c) conflict-free.
        float cq[8];
#pragma unroll
        for (int cc = 0; cc < 8; cc++) cq[cc] = csq[(tx << 3) + cc];
#pragma unroll
        for (int p = 0; p < 4; p++) {
            int r0 = (ty << 3) + 2 * p;
#pragma unroll
            for (int cc = 0; cc < 8; cc++) {
                float2 d = unpack2(acc[p * 8 + cc]);
                acc[p * 8 + cc] = 0ull;
                int c = (tx << 3) + cc;            // c>>3 == tx (cc<8)
                float d2a = fmaxf((sqn[2 * p]     + cq[cc]) - 2.0f * d.x, 0.0f);
                float d2b = fmaxf((sqn[2 * p + 1] + cq[cc]) - 2.0f * d.y, 0.0f);
                cs[(c << 6) + (r0 ^ tx)]       = d2a;
                cs[(c << 6) + ((r0 + 1) ^ tx)] = d2b;
            }
        }
        __syncthreads();

        // ---- scan: thread handles row srow, candidate half `half`,
        // ascending j -> ascending global idx -> strict < keeps ref tie order.
#pragma unroll 4
        for (int j = 0; j < CT / 2; j++) {
            int c = (half << 6) + j;
            float v = cs[(c << 6) + (srow ^ (c >> 3))];
            if (v < bd[KK - 1]) {
                float vv = v;
                int   vi = t0 + c;
#pragma unroll
                for (int s = 0; s < KK; s++) {
                    bool sw = vv < bd[s];
                    float tv = bd[s];
                    int   ti = bi[s];
                    if (sw) { bd[s] = vv; bi[s] = vi; vv = tv; vi = ti; }
                }
            }
        }
    }

    // ---- merge the two half-lists per row (both sorted by (d2, idx)).
    __syncthreads();
    float* md = qs;            // [64][2][9] distances  (qs is dead now)
    float* mi = qs + 64 * 2 * KK;  // [64][2][9] indices (as float)
    {
        int slot = ((srow << 1) + half) * KK;
#pragma unroll
        for (int i = 0; i < KK; i++) {
            md[slot + i] = bd[i];
            mi[slot + i] = (float)bi[i];
        }
    }
    __syncthreads();

    if (tid < QT) {
        const float* dA = md + (tid << 1) * KK;
        const float* dB = dA + KK;
        const float* iA = mi + (tid << 1) * KK;
        const float* iB = iA + KK;
        const size_t o = (base + q0 + tid) * KK;
        int pa = 0, pb = 0;
#pragma unroll
        for (int i = 0; i < KK; i++) {
            float da = dA[pa], db = dB[pb];
            float ia = iA[pa], ib = iB[pb];
            bool takeA = (da < db) || (da == db && ia < ib);  // tie: lower idx
            out[o + i] = takeA ? ia : ib;
            pa += takeA ? 1 : 0;
            pb += takeA ? 0 : 1;
            out[(size_t)BB * NN * KK + o + i] = (float)(q0 + tid);
        }
    }
}

extern "C" void kernel_launch(void* const* d_in, const int* in_sizes, int n_in,
                              void* d_out, int out_size) {
    int best = 0, best_sz = -1;
    for (int i = 0; i < n_in; i++) {
        if (in_sizes[i] == BB * DD * NN) { best = i; best_sz = in_sizes[i]; break; }
        if (in_sizes[i] > best_sz) { best_sz = in_sizes[i]; best = i; }
    }
    const float* x = (const float*)d_in[best];
    float* out = (float*)d_out;

    normalize_kernel<<<(BB * NN + 255) / 256, 256>>>(x);
    knn_kernel<<<(BB * NN) / QT, NTHR>>>(out);
}

// round 15
// speedup vs baseline: 1.0054x; 1.0054x over previous
#include <cuda_runtime.h>

// DenseDilatedKnnGraph: x (4,64,8192,1) fp32 -> edge_index (2,4,8192,9)
// k=9, dilation=1. Output buffer FLOAT32 (confirmed; indices exactly repr.).
//
// R15: 128-thread CTAs with R9's per-warp geometry (4 row-groups x 8 cand-
// groups per warp; warps tiled 2x2 over 64 rows x 128 cands) + manually
// software-pipelined mainloop (prefetch k+1 regs before k's FFMA2 block).

#define BB 4
#define DD 64
#define NN 8192
#define KK 9
#define CT 128         // candidates per tile
#define QT 64          // query rows per CTA
#define NTHR 128

typedef unsigned long long u64;

__device__ __align__(16) float g_ptsT[(size_t)BB * DD * NN];  // [b][d][n], 8 MB
__device__ float g_sq[BB * NN];

__device__ __forceinline__ u64 ffma2(u64 a, u64 b, u64 c) {
    u64 d;
    asm("fma.rn.f32x2 %0, %1, %2, %3;" : "=l"(d) : "l"(a), "l"(b), "l"(c));
    return d;
}
__device__ __forceinline__ u64 pack2(float v) {
    u64 d;
    asm("mov.b64 %0, {%1, %1};" : "=l"(d) : "f"(v));
    return d;
}
__device__ __forceinline__ float2 unpack2(u64 a) {
    float2 f;
    asm("mov.b64 {%0, %1}, %2;" : "=f"(f.x), "=f"(f.y) : "l"(a));
    return f;
}

// ---------------------------------------------------------------------------
// Stage 1: normalize + transpose to [b][d][n]. One thread per point.
// ---------------------------------------------------------------------------
__global__ void __launch_bounds__(256) normalize_kernel(const float* __restrict__ x) {
    int idx = blockIdx.x * blockDim.x + threadIdx.x;
    if (idx >= BB * NN) return;
    int b = idx / NN;
    int n = idx - b * NN;
    const float* xb = x + (size_t)b * DD * NN + n;
    float* pb = g_ptsT + (size_t)b * DD * NN + n;

    float v[DD];
    float s = 0.0f;
#pragma unroll
    for (int d = 0; d < DD; d++) {
        v[d] = xb[(size_t)d * NN];
        s += v[d] * v[d];
    }
    float nrm = fmaxf(sqrtf(s), 1e-12f);
    float s2 = 0.0f;
#pragma unroll
    for (int d = 0; d < DD; d++) {
        float xn = v[d] / nrm;
        pb[(size_t)d * NN] = xn;
        s2 += xn * xn;
    }
    g_sq[idx] = s2;
}

// ---------------------------------------------------------------------------
// Stage 2: tiled brute-force KNN.
// Warp w (lane l): row group rg = (w&1)*4 + (l>>3)  -> rows rg*8..+7
//                  cand group cg = (w>>1)*8 + (l&7) -> cands cg*8..+7
// ---------------------------------------------------------------------------
__global__ void __launch_bounds__(NTHR, 3) knn_kernel(float* __restrict__ out) {
    __shared__ __align__(16) float qs[QT * DD];   // [k][row]  16 KB (merge buf later)
    __shared__ __align__(16) float cs[CT * DD];   // [k][cand] 32 KB; d2 tile after compute
    __shared__ float csq[CT];

    const int tid = threadIdx.x;
    const int w = tid >> 5, l = tid & 31;
    const int ty = ((w & 1) << 2) | (l >> 3);   // 0..7 row group
    const int tx = ((w >> 1) << 3) | (l & 7);   // 0..15 cand group
    const int blk = blockIdx.x;                 // 0..511
    const int b = blk >> 7;
    const int q0 = (blk & 127) << 6;
    const float* __restrict__ ptsT = g_ptsT + (size_t)b * DD * NN;
    const size_t base = (size_t)b * NN;

    // q tile: qs[k][r] = ptsT[k][q0+r]; 1024 float4, coalesced.
#pragma unroll
    for (int i = 0; i < 8; i++) {
        int f = tid + (i << 7);
        int k = f >> 4, j4 = f & 15;
        ((float4*)qs)[f] = ((const float4*)(ptsT + (size_t)k * NN + q0))[j4];
    }
    float sqn[8];
#pragma unroll
    for (int rr = 0; rr < 8; rr++) sqn[rr] = g_sq[base + q0 + (ty << 3) + rr];

    // per-thread scan stream: row (tid&63), candidate half (tid>>6)
    const int srow = tid & 63;
    const int half = tid >> 6;
    float bd[KK];
    int   bi[KK];
#pragma unroll
    for (int i = 0; i < KK; i++) { bd[i] = 3.4e38f; bi[i] = 0; }

    u64 acc[32];                       // [row_pair p 0..3][cand cc 0..7]
#pragma unroll
    for (int i = 0; i < 32; i++) acc[i] = 0ull;

    for (int t0 = 0; t0 < NN; t0 += CT) {
        __syncthreads();               // prev scan done; safe to overwrite cs
#pragma unroll
        for (int i = 0; i < 16; i++) {
            int f = tid + (i << 7);        // 0..2047 float4
            int k = f >> 5, j4 = f & 31;
            ((float4*)cs)[f] = ((const float4*)(ptsT + (size_t)k * NN + t0))[j4];
        }
        csq[tid] = g_sq[base + t0 + tid];
        __syncthreads();

        // ---- mainloop, software-pipelined: prefetch k+1 before k's FFMA2s.
        const float* qb0 = qs + (ty << 3);
        const float* cb0 = cs + (tx << 3);
        ulonglong2 qA = *(const ulonglong2*)(qb0);
        ulonglong2 qB = *(const ulonglong2*)(qb0 + 4);
        float4 cA = *(const float4*)(cb0);
        float4 cB = *(const float4*)(cb0 + 4);
#pragma unroll 4
        for (int k = 0; k < DD; k++) {
            int kn = (k + 1) & (DD - 1);           // wrap: k=63 reloads k=0 (unused)
            const float* qk = qb0 + (kn << 6);
            const float* ck = cb0 + (kn << 7);
            ulonglong2 nqA = *(const ulonglong2*)(qk);
            ulonglong2 nqB = *(const ulonglong2*)(qk + 4);
            float4 ncA = *(const float4*)(ck);
            float4 ncB = *(const float4*)(ck + 4);

            u64 cd[8];
            cd[0] = pack2(cA.x); cd[1] = pack2(cA.y);
            cd[2] = pack2(cA.z); cd[3] = pack2(cA.w);
            cd[4] = pack2(cB.x); cd[5] = pack2(cB.y);
            cd[6] = pack2(cB.z); cd[7] = pack2(cB.w);
#pragma unroll
            for (int c = 0; c < 8; c++) {
                acc[0 * 8 + c] = ffma2(qA.x, cd[c], acc[0 * 8 + c]);
                acc[1 * 8 + c] = ffma2(qA.y, cd[c], acc[1 * 8 + c]);
                acc[2 * 8 + c] = ffma2(qB.x, cd[c], acc[2 * 8 + c]);
                acc[3 * 8 + c] = ffma2(qB.y, cd[c], acc[3 * 8 + c]);
            }
            qA = nqA; qB = nqB; cA = ncA; cB = ncB;   // renamed away by unroll
        }
        __syncthreads();               // all reads of cs done

        // ---- epilogue: d2 -> swizzled smem aliasing cs.
        // d2[r][c] at word c*64 + (r ^ (c>>3)); conflict-free scatter AND scan
        // for this warp mapping (bank = (r^cg)&31 bijective over lanes).
        float cq[8];
#pragma unroll
        for (int cc = 0; cc < 8; cc++) cq[cc] = csq[(tx << 3) + cc];
#pragma unroll
        for (int p = 0; p < 4; p++) {
            int r0 = (ty << 3) + 2 * p;
#pragma unroll
            for (int cc = 0; cc < 8; cc++) {
                float2 d = unpack2(acc[p * 8 + cc]);
                acc[p * 8 + cc] = 0ull;
                int c = (tx << 3) + cc;            // c>>3 == tx
                float d2a = fmaxf((sqn[2 * p]     + cq[cc]) - 2.0f * d.x, 0.0f);
                float d2b = fmaxf((sqn[2 * p + 1] + cq[cc]) - 2.0f * d.y, 0.0f);
                cs[(c << 6) + (r0 ^ tx)]       = d2a;
                cs[(c << 6) + ((r0 + 1) ^ tx)] = d2b;
            }
        }
        __syncthreads();

        // ---- scan: row srow, candidate half; ascending j keeps exact
        // reference tie order within each half (strict <).
#pragma unroll 4
        for (int j = 0; j < CT / 2; j++) {
            int c = (half << 6) + j;
            float v = cs[(c << 6) + (srow ^ (c >> 3))];
            if (v < bd[KK - 1]) {
                float vv = v;
                int   vi = t0 + c;
#pragma unroll
                for (int s = 0; s < KK; s++) {
                    bool sw = vv < bd[s];
                    float tv = bd[s];
                    int   ti = bi[s];
                    if (sw) { bd[s] = vv; bi[s] = vi; vv = tv; vi = ti; }
                }
            }
        }
    }

    // ---- merge the two per-row half-lists (both sorted by (d2, idx)).
    __syncthreads();
    float* md = qs;                    // [64][2][9] distances (qs dead)
    float* mi = qs + 64 * 2 * KK;      // [64][2][9] indices
    {
        int slot = ((srow << 1) + half) * KK;
#pragma unroll
        for (int i = 0; i < KK; i++) {
            md[slot + i] = bd[i];
            mi[slot + i] = (float)bi[i];
        }
    }
    __syncthreads();

    if (tid < QT) {
        const float* dA = md + (tid << 1) * KK;
        const float* dB = dA + KK;
        const float* iA = mi + (tid << 1) * KK;
        const float* iB = iA + KK;
        const size_t o = (base + q0 + tid) * KK;
        int pa = 0, pb = 0;
#pragma unroll
        for (int i = 0; i < KK; i++) {
            float da = dA[pa], db = dB[pb];
            float ia = iA[pa], ib = iB[pb];
            bool takeA = (da < db) || (da == db && ia < ib);  // tie: lower idx
            out[o + i] = takeA ? ia : ib;
            pa += takeA ? 1 : 0;
            pb += takeA ? 0 : 1;
            out[(size_t)BB * NN * KK + o + i] = (float)(q0 + tid);
        }
    }
}

extern "C" void kernel_launch(void* const* d_in, const int* in_sizes, int n_in,
                              void* d_out, int out_size) {
    int best = 0, best_sz = -1;
    for (int i = 0; i < n_in; i++) {
        if (in_sizes[i] == BB * DD * NN) { best = i; best_sz = in_sizes[i]; break; }
        if (in_sizes[i] > best_sz) { best_sz = in_sizes[i]; best = i; }
    }
    const float* x = (const float*)d_in[best];
    float* out = (float*)d_out;

    normalize_kernel<<<(BB * NN + 255) / 256, 256>>>(x);
    knn_kernel<<<(BB * NN) / QT, NTHR>>>(out);
}